// round 3
// baseline (speedup 1.0000x reference)
#include <cuda_runtime.h>
#include <math.h>

#define NUM_USERS 60000
#define NUM_ITEMS 40000
#define NUM_NODES 100000
#define EMB 64
#define HID 32
#define N_EDGES 1600000
#define BATCH 16384

// Scratch (allocation-free rule: device globals)
__device__ __align__(16) float g_h1[NUM_NODES * HID];     // lin1 output (pre-agg)
__device__ __align__(16) float g_agg1[NUM_NODES * HID];   // segment-sum layer 1
__device__ __align__(16) float g_h2lin[NUM_NODES * EMB];  // lin2 output (pre-agg)

// ---------------------------------------------------------------------------
// K1: h1[n][j] = sum_k feat[n][k] * gc1_w[j][k] + gc1_b[j]
// warp per node, lane = output j
__global__ void lin1_kernel(const float* __restrict__ uemb,
                            const float* __restrict__ iemb,
                            const float* __restrict__ W,
                            const float* __restrict__ b) {
    __shared__ float sW[HID][EMB + 1];  // pad to kill bank conflicts
    int tid = threadIdx.x;
    for (int i = tid; i < HID * EMB; i += blockDim.x)
        sW[i / EMB][i % EMB] = W[i];
    __syncthreads();

    int lane = tid & 31;
    int node = blockIdx.x * (blockDim.x >> 5) + (tid >> 5);
    if (node >= NUM_NODES) return;

    const float4* feat = (node < NUM_USERS)
        ? (const float4*)(uemb + (size_t)node * EMB)
        : (const float4*)(iemb + (size_t)(node - NUM_USERS) * EMB);

    float acc = b[lane];
#pragma unroll
    for (int k4 = 0; k4 < EMB / 4; k4++) {
        float4 x = __ldg(&feat[k4]);
        acc += x.x * sW[lane][k4 * 4 + 0];
        acc += x.y * sW[lane][k4 * 4 + 1];
        acc += x.z * sW[lane][k4 * 4 + 2];
        acc += x.w * sW[lane][k4 * 4 + 3];
    }
    g_h1[(size_t)node * HID + lane] = acc;
}

// ---------------------------------------------------------------------------
// zero n floats (n % 4 == 0), float4 stores
__global__ void zero_kernel(float4* __restrict__ p, int n4) {
    int i = blockIdx.x * blockDim.x + threadIdx.x;
    if (i < n4) p[i] = make_float4(0.f, 0.f, 0.f, 0.f);
}

// ---------------------------------------------------------------------------
// K3: edge scatter, layer 1 (HID=32 feats). 8 threads per edge (float4 each)
__global__ void scatter1_kernel(const int* __restrict__ rows,
                                const int* __restrict__ cols,
                                const float* __restrict__ vals) {
    int idx = blockIdx.x * blockDim.x + threadIdx.x;
    int e = idx >> 3;
    int f4 = idx & 7;
    if (e >= N_EDGES) return;
    int r = __ldg(&rows[e]);
    int c = __ldg(&cols[e]);
    float v = __ldg(&vals[e]);
    float4 h = ((const float4*)g_h1)[(size_t)c * (HID / 4) + f4];
    float* dst = g_agg1 + (size_t)r * HID + f4 * 4;
    atomicAdd(dst + 0, v * h.x);
    atomicAdd(dst + 1, v * h.y);
    atomicAdd(dst + 2, v * h.z);
    atomicAdd(dst + 3, v * h.w);
}

// ---------------------------------------------------------------------------
// K4: h2lin[n][j] = sum_k relu(agg1[n][k]) * gc2_w[j][k] + gc2_b[j]
// warp per node; lane handles j = lane and j = lane+32
__global__ void lin2_kernel(const float* __restrict__ W2,
                            const float* __restrict__ b2) {
    __shared__ float sW[EMB][HID + 1];
    int tid = threadIdx.x;
    for (int i = tid; i < EMB * HID; i += blockDim.x)
        sW[i / HID][i % HID] = W2[i];
    __syncthreads();

    int lane = tid & 31;
    int node = blockIdx.x * (blockDim.x >> 5) + (tid >> 5);
    if (node >= NUM_NODES) return;

    const float4* hin = (const float4*)(g_agg1 + (size_t)node * HID);
    float acc0 = b2[lane];
    float acc1 = b2[lane + 32];
#pragma unroll
    for (int k4 = 0; k4 < HID / 4; k4++) {
        float4 x = hin[k4];
        x.x = fmaxf(x.x, 0.f);
        x.y = fmaxf(x.y, 0.f);
        x.z = fmaxf(x.z, 0.f);
        x.w = fmaxf(x.w, 0.f);
        acc0 += x.x * sW[lane][k4 * 4 + 0] + x.y * sW[lane][k4 * 4 + 1]
              + x.z * sW[lane][k4 * 4 + 2] + x.w * sW[lane][k4 * 4 + 3];
        acc1 += x.x * sW[lane + 32][k4 * 4 + 0] + x.y * sW[lane + 32][k4 * 4 + 1]
              + x.z * sW[lane + 32][k4 * 4 + 2] + x.w * sW[lane + 32][k4 * 4 + 3];
    }
    g_h2lin[(size_t)node * EMB + lane] = acc0;
    g_h2lin[(size_t)node * EMB + lane + 32] = acc1;
}

// ---------------------------------------------------------------------------
// K6: edge scatter, layer 2 (EMB=64 feats). 16 threads per edge (float4 each)
__global__ void scatter2_kernel(const int* __restrict__ rows,
                                const int* __restrict__ cols,
                                const float* __restrict__ vals,
                                float* __restrict__ out_h2) {
    int idx = blockIdx.x * blockDim.x + threadIdx.x;
    int e = idx >> 4;
    int f4 = idx & 15;
    if (e >= N_EDGES) return;
    int r = __ldg(&rows[e]);
    int c = __ldg(&cols[e]);
    float v = __ldg(&vals[e]);
    float4 h = ((const float4*)g_h2lin)[(size_t)c * (EMB / 4) + f4];
    float* dst = out_h2 + (size_t)r * EMB + f4 * 4;
    atomicAdd(dst + 0, v * h.x);
    atomicAdd(dst + 1, v * h.y);
    atomicAdd(dst + 2, v * h.z);
    atomicAdd(dst + 3, v * h.w);
}

// ---------------------------------------------------------------------------
// K7: relu in place (float4)
__global__ void relu_kernel(float4* __restrict__ p, int n4) {
    int i = blockIdx.x * blockDim.x + threadIdx.x;
    if (i < n4) {
        float4 x = p[i];
        x.x = fmaxf(x.x, 0.f);
        x.y = fmaxf(x.y, 0.f);
        x.z = fmaxf(x.z, 0.f);
        x.w = fmaxf(x.w, 0.f);
        p[i] = x;
    }
}

// ---------------------------------------------------------------------------
// K8: prediction MLP. warp per batch sample; lane = hidden unit j (32)
__global__ void predict_kernel(const int* __restrict__ uid,
                               const int* __restrict__ iid,
                               const float* __restrict__ h2,
                               const float* __restrict__ p1w,
                               const float* __restrict__ p1b,
                               const float* __restrict__ p2w,
                               const float* __restrict__ p2b,
                               float* __restrict__ scores) {
    __shared__ float sP1[HID][2 * EMB + 1];  // 32 x 129
    __shared__ float sP2[HID];
    int tid = threadIdx.x;
    for (int i = tid; i < HID * 2 * EMB; i += blockDim.x)
        sP1[i / (2 * EMB)][i % (2 * EMB)] = p1w[i];
    if (tid < HID) sP2[tid] = p2w[tid];
    __syncthreads();

    int lane = tid & 31;
    int s = blockIdx.x * (blockDim.x >> 5) + (tid >> 5);
    if (s >= BATCH) return;

    int u = __ldg(&uid[s]);
    int it = __ldg(&iid[s]);
    const float4* bu = (const float4*)(h2 + (size_t)u * EMB);
    const float4* bi = (const float4*)(h2 + (size_t)(NUM_USERS + it) * EMB);

    float acc = p1b[lane];
#pragma unroll
    for (int k4 = 0; k4 < EMB / 4; k4++) {
        float4 x = __ldg(&bu[k4]);
        acc += x.x * sP1[lane][k4 * 4 + 0] + x.y * sP1[lane][k4 * 4 + 1]
             + x.z * sP1[lane][k4 * 4 + 2] + x.w * sP1[lane][k4 * 4 + 3];
    }
#pragma unroll
    for (int k4 = 0; k4 < EMB / 4; k4++) {
        float4 x = __ldg(&bi[k4]);
        acc += x.x * sP1[lane][EMB + k4 * 4 + 0] + x.y * sP1[lane][EMB + k4 * 4 + 1]
             + x.z * sP1[lane][EMB + k4 * 4 + 2] + x.w * sP1[lane][EMB + k4 * 4 + 3];
    }
    float z = fmaxf(acc, 0.f);
    float ssum = z * sP2[lane];
#pragma unroll
    for (int o = 16; o > 0; o >>= 1)
        ssum += __shfl_xor_sync(0xffffffffu, ssum, o);
    if (lane == 0)
        scores[s] = 1.f / (1.f + expf(-(ssum + p2b[0])));
}

// ---------------------------------------------------------------------------
extern "C" void kernel_launch(void* const* d_in, const int* in_sizes, int n_in,
                              void* d_out, int out_size) {
    const int*   user_ids = (const int*)d_in[0];
    const int*   item_ids = (const int*)d_in[1];
    const int*   adj_rows = (const int*)d_in[2];
    const int*   adj_cols = (const int*)d_in[3];
    const float* adj_vals = (const float*)d_in[4];
    const float* uemb     = (const float*)d_in[5];
    const float* iemb     = (const float*)d_in[6];
    const float* gc1w     = (const float*)d_in[7];
    const float* gc1b     = (const float*)d_in[8];
    const float* gc2w     = (const float*)d_in[9];
    const float* gc2b     = (const float*)d_in[10];
    const float* p1w      = (const float*)d_in[11];
    const float* p1b      = (const float*)d_in[12];
    const float* p2w      = (const float*)d_in[13];
    const float* p2b      = (const float*)d_in[14];

    float* out = (float*)d_out;
    float* out_h2 = out + BATCH;  // [NUM_NODES * EMB] = concat(user_emb, item_emb)

    float* d_agg1;
    cudaGetSymbolAddress((void**)&d_agg1, g_agg1);

    const int TB = 256;

    // L1 linear
    lin1_kernel<<<NUM_NODES / 8, TB>>>(uemb, iemb, gc1w, gc1b);
    // zero agg1
    zero_kernel<<<(NUM_NODES * HID / 4) / TB, TB>>>((float4*)d_agg1, NUM_NODES * HID / 4);
    // edge scatter L1: 8 threads/edge
    scatter1_kernel<<<(N_EDGES * 8) / TB, TB>>>(adj_rows, adj_cols, adj_vals);
    // L2 linear (fused relu on input)
    lin2_kernel<<<NUM_NODES / 8, TB>>>(gc2w, gc2b);
    // zero output h2 region
    zero_kernel<<<(NUM_NODES * EMB / 4) / TB, TB>>>((float4*)out_h2, NUM_NODES * EMB / 4);
    // edge scatter L2: 16 threads/edge
    scatter2_kernel<<<(N_EDGES * 16) / TB, TB>>>(adj_rows, adj_cols, adj_vals, out_h2);
    // relu in place on output embeddings
    relu_kernel<<<(NUM_NODES * EMB / 4) / TB, TB>>>((float4*)out_h2, NUM_NODES * EMB / 4);
    // prediction head
    predict_kernel<<<BATCH / 8, TB>>>(user_ids, item_ids, out_h2,
                                      p1w, p1b, p2w, p2b, out);
}

// round 4
// speedup vs baseline: 1.4496x; 1.4496x over previous
#include <cuda_runtime.h>
#include <math.h>

#define NUM_USERS 60000
#define NUM_ITEMS 40000
#define NUM_NODES 100000
#define EMB 64
#define HID 32
#define N_EDGES 1600000
#define BATCH 16384

#define SCAN_BLK 1024
#define NB ((NUM_NODES + SCAN_BLK - 1) / SCAN_BLK)   // 98

// ---------------- device scratch (allocation-free rule) ----------------
__device__ __align__(16) float g_h1[NUM_NODES * HID];      // lin1 output
__device__ __align__(16) float g_h2lin[NUM_NODES * EMB];   // lin2 output (pre-agg2)
__device__ int   g_counts[NUM_NODES];                      // degree hist, reused as cursor
__device__ int   g_row_ptr[NUM_NODES + 1];
__device__ int   g_block_sums[NB];
__device__ __align__(8) int2 g_epk[N_EDGES];               // packed (col, val-bits), CSR order

// ---------------------------------------------------------------------------
// lin1: h1[n][j] = feat[n] . W1[j] + b1[j].  Persistent, weights in registers,
// activations broadcast via shuffle (no LDS).
__global__ void lin1_kernel(const float* __restrict__ uemb,
                            const float* __restrict__ iemb,
                            const float* __restrict__ W,
                            const float* __restrict__ b) {
    int lane = threadIdx.x & 31;
    float w[EMB];
#pragma unroll
    for (int k = 0; k < EMB; k++) w[k] = __ldg(&W[lane * EMB + k]);
    float bias = __ldg(&b[lane]);

    int warp   = blockIdx.x * (blockDim.x >> 5) + (threadIdx.x >> 5);
    int nwarps = gridDim.x * (blockDim.x >> 5);

    for (int node = warp; node < NUM_NODES; node += nwarps) {
        const float* feat = (node < NUM_USERS)
            ? uemb + (size_t)node * EMB
            : iemb + (size_t)(node - NUM_USERS) * EMB;
        float x0 = __ldg(&feat[lane]);
        float x1 = __ldg(&feat[lane + 32]);
        float acc = bias;
#pragma unroll
        for (int k = 0; k < 32; k++) {
            acc += __shfl_sync(0xffffffffu, x0, k) * w[k];
            acc += __shfl_sync(0xffffffffu, x1, k) * w[k + 32];
        }
        g_h1[(size_t)node * HID + lane] = acc;
    }
}

// ---------------------------------------------------------------------------
// CSR build
__global__ void zero_counts_kernel() {
    int i = blockIdx.x * blockDim.x + threadIdx.x;
    if (i < NUM_NODES) g_counts[i] = 0;
}

__global__ void hist_kernel(const int* __restrict__ rows) {
    int e = blockIdx.x * blockDim.x + threadIdx.x;
    if (e < N_EDGES) atomicAdd(&g_counts[rows[e]], 1);
}

// block-wise inclusive scan -> exclusive per element; block totals out
__global__ void scan1_kernel() {
    __shared__ int sh[SCAN_BLK];
    int tid = threadIdx.x;
    int i = blockIdx.x * SCAN_BLK + tid;
    int v = (i < NUM_NODES) ? g_counts[i] : 0;
    sh[tid] = v;
    __syncthreads();
#pragma unroll
    for (int off = 1; off < SCAN_BLK; off <<= 1) {
        int t = (tid >= off) ? sh[tid - off] : 0;
        __syncthreads();
        sh[tid] += t;
        __syncthreads();
    }
    if (i < NUM_NODES) g_row_ptr[i] = sh[tid] - v;      // exclusive
    if (tid == SCAN_BLK - 1) g_block_sums[blockIdx.x] = sh[tid];
}

// scan the 98 block sums (exclusive), single block of 128 threads
__global__ void scan2_kernel() {
    __shared__ int sh[128];
    int tid = threadIdx.x;
    int v = (tid < NB) ? g_block_sums[tid] : 0;
    sh[tid] = v;
    __syncthreads();
#pragma unroll
    for (int off = 1; off < 128; off <<= 1) {
        int t = (tid >= off) ? sh[tid - off] : 0;
        __syncthreads();
        sh[tid] += t;
        __syncthreads();
    }
    if (tid < NB) g_block_sums[tid] = sh[tid] - v;      // exclusive
}

// add block offsets; init cursor = row_ptr; finalize row_ptr[NN]
__global__ void scan3_kernel() {
    int i = blockIdx.x * blockDim.x + threadIdx.x;
    if (i < NUM_NODES) {
        int rp = g_row_ptr[i] + g_block_sums[i / SCAN_BLK];
        g_row_ptr[i] = rp;
        g_counts[i]  = rp;          // cursor for permute
    }
    if (i == 0) g_row_ptr[NUM_NODES] = N_EDGES;
}

__global__ void permute_kernel(const int* __restrict__ rows,
                               const int* __restrict__ cols,
                               const float* __restrict__ vals) {
    int e = blockIdx.x * blockDim.x + threadIdx.x;
    if (e >= N_EDGES) return;
    int r = rows[e];
    int pos = atomicAdd(&g_counts[r], 1);
    g_epk[pos] = make_int2(cols[e], __float_as_int(vals[e]));
}

// ---------------------------------------------------------------------------
// SpMM layer 1 + fused ReLU + fused lin2.  Warp per row; lane = feature k.
// After aggregation the row vector lives one-value-per-lane -> do the
// [64x32] lin2 with 32 shuffles, write h2lin directly.
__global__ void spmm1_lin2_kernel(const float* __restrict__ W2,
                                  const float* __restrict__ b2) {
    int lane = threadIdx.x & 31;
    float w0[HID], w1[HID];
#pragma unroll
    for (int k = 0; k < HID; k++) {
        w0[k] = __ldg(&W2[lane * HID + k]);
        w1[k] = __ldg(&W2[(lane + 32) * HID + k]);
    }
    float b0 = __ldg(&b2[lane]);
    float b1 = __ldg(&b2[lane + 32]);

    int warp   = blockIdx.x * (blockDim.x >> 5) + (threadIdx.x >> 5);
    int nwarps = gridDim.x * (blockDim.x >> 5);

    for (int r = warp; r < NUM_NODES; r += nwarps) {
        int jb = g_row_ptr[r], je = g_row_ptr[r + 1];
        float acc = 0.f;
        for (int j = jb; j < je; j++) {
            int2 cv = g_epk[j];                       // warp-uniform broadcast
            acc += __int_as_float(cv.y) * g_h1[(size_t)cv.x * HID + lane];
        }
        float x = fmaxf(acc, 0.f);                    // fused ReLU
        float o0 = b0, o1 = b1;
#pragma unroll
        for (int k = 0; k < 32; k++) {
            float xk = __shfl_sync(0xffffffffu, x, k);
            o0 += xk * w0[k];
            o1 += xk * w1[k];
        }
        g_h2lin[(size_t)r * EMB + lane]      = o0;
        g_h2lin[(size_t)r * EMB + lane + 32] = o1;
    }
}

// ---------------------------------------------------------------------------
// SpMM layer 2 + fused ReLU, writes final embeddings straight into d_out.
// Warp per row; lane covers features {lane, lane+32}.
__global__ void spmm2_kernel(float* __restrict__ out_h2) {
    int lane = threadIdx.x & 31;
    int warp   = blockIdx.x * (blockDim.x >> 5) + (threadIdx.x >> 5);
    int nwarps = gridDim.x * (blockDim.x >> 5);

    for (int r = warp; r < NUM_NODES; r += nwarps) {
        int jb = g_row_ptr[r], je = g_row_ptr[r + 1];
        float a0 = 0.f, a1 = 0.f;
        for (int j = jb; j < je; j++) {
            int2 cv = g_epk[j];
            float v = __int_as_float(cv.y);
            const float* hrow = g_h2lin + (size_t)cv.x * EMB;
            a0 += v * hrow[lane];
            a1 += v * hrow[lane + 32];
        }
        out_h2[(size_t)r * EMB + lane]      = fmaxf(a0, 0.f);
        out_h2[(size_t)r * EMB + lane + 32] = fmaxf(a1, 0.f);
    }
}

// ---------------------------------------------------------------------------
// prediction MLP. warp per batch sample; lane = hidden unit
__global__ void predict_kernel(const int* __restrict__ uid,
                               const int* __restrict__ iid,
                               const float* __restrict__ h2,
                               const float* __restrict__ p1w,
                               const float* __restrict__ p1b,
                               const float* __restrict__ p2w,
                               const float* __restrict__ p2b,
                               float* __restrict__ scores) {
    int lane = threadIdx.x & 31;
    // lane j holds p1_w[j][0:128] in registers
    float w[2 * EMB];
#pragma unroll
    for (int k = 0; k < 2 * EMB; k++) w[k] = __ldg(&p1w[lane * 2 * EMB + k]);
    float bias = __ldg(&p1b[lane]);
    float w2   = __ldg(&p2w[lane]);
    float b2v  = __ldg(&p2b[0]);

    int warp   = blockIdx.x * (blockDim.x >> 5) + (threadIdx.x >> 5);
    int nwarps = gridDim.x * (blockDim.x >> 5);

    for (int s = warp; s < BATCH; s += nwarps) {
        int u  = __ldg(&uid[s]);
        int it = __ldg(&iid[s]);
        const float* bu = h2 + (size_t)u * EMB;
        const float* bi = h2 + (size_t)(NUM_USERS + it) * EMB;
        float x0 = bu[lane], x1 = bu[lane + 32];
        float x2 = bi[lane], x3 = bi[lane + 32];
        float acc = bias;
#pragma unroll
        for (int k = 0; k < 32; k++) {
            acc += __shfl_sync(0xffffffffu, x0, k) * w[k];
            acc += __shfl_sync(0xffffffffu, x1, k) * w[k + 32];
            acc += __shfl_sync(0xffffffffu, x2, k) * w[k + 64];
            acc += __shfl_sync(0xffffffffu, x3, k) * w[k + 96];
        }
        float z = fmaxf(acc, 0.f) * w2;
#pragma unroll
        for (int o = 16; o > 0; o >>= 1)
            z += __shfl_xor_sync(0xffffffffu, z, o);
        if (lane == 0)
            scores[s] = 1.f / (1.f + expf(-(z + b2v)));
    }
}

// ---------------------------------------------------------------------------
extern "C" void kernel_launch(void* const* d_in, const int* in_sizes, int n_in,
                              void* d_out, int out_size) {
    const int*   user_ids = (const int*)d_in[0];
    const int*   item_ids = (const int*)d_in[1];
    const int*   adj_rows = (const int*)d_in[2];
    const int*   adj_cols = (const int*)d_in[3];
    const float* adj_vals = (const float*)d_in[4];
    const float* uemb     = (const float*)d_in[5];
    const float* iemb     = (const float*)d_in[6];
    const float* gc1w     = (const float*)d_in[7];
    const float* gc1b     = (const float*)d_in[8];
    const float* gc2w     = (const float*)d_in[9];
    const float* gc2b     = (const float*)d_in[10];
    const float* p1w      = (const float*)d_in[11];
    const float* p1b      = (const float*)d_in[12];
    const float* p2w      = (const float*)d_in[13];
    const float* p2b      = (const float*)d_in[14];

    float* out    = (float*)d_out;
    float* out_h2 = out + BATCH;   // [NUM_NODES*EMB] = concat(user_emb, item_emb)

    const int TB = 256;

    // lin1 (independent of CSR build; persistent shuffle kernel)
    lin1_kernel<<<296, TB>>>(uemb, iemb, gc1w, gc1b);

    // ---- CSR build ----
    zero_counts_kernel<<<(NUM_NODES + TB - 1) / TB, TB>>>();
    hist_kernel<<<(N_EDGES + TB - 1) / TB, TB>>>(adj_rows);
    scan1_kernel<<<NB, SCAN_BLK>>>();
    scan2_kernel<<<1, 128>>>();
    scan3_kernel<<<(NUM_NODES + TB - 1) / TB, TB>>>();
    permute_kernel<<<(N_EDGES + TB - 1) / TB, TB>>>(adj_rows, adj_cols, adj_vals);

    // ---- layer 1 aggregate + ReLU + lin2 (fused) ----
    spmm1_lin2_kernel<<<592, TB>>>(gc2w, gc2b);

    // ---- layer 2 aggregate + ReLU -> d_out ----
    spmm2_kernel<<<592, TB>>>(out_h2);

    // ---- prediction head ----
    predict_kernel<<<148, TB>>>(user_ids, item_ids, out_h2,
                                p1w, p1b, p2w, p2b, out);
}